// round 11
// baseline (speedup 1.0000x reference)
#include <cuda_runtime.h>

// AtteMatchLay: multi-perspective cosine similarity.
// out[n][p] = dot / (max(sqrt(n1),eps) * max(sqrt(n2),eps))
//   dot = sum_d r[n][d]*m[n][d]*w2[p][d]
//   n1  = sum_d r^2 * w2,  n2 = sum_d m^2 * w2,  w2 = weight^2
// N = 8192 rows, D = 768, P = 20. fp32 in/out.
//
// Warp = 4 rows x 8 d-lanes. w^2 staged transposed [D][P] in shared with a
// block-local swizzle (injective; zero bank conflicts; see R7).
// Accumulators packed f32x2 over p-pairs via fma.rn.f32x2.
//
// R8 (resubmit after infra flake "system not yet initialized"):
// 224-thread blocks (7 warps = 28 rows), grid 293 = one balanced wave
// across 148 SMs at 2 CTAs/SM, and the 2-CTA register cap rises 128 -> 146,
// giving ptxas slack to software-pipeline the per-j wv loads.

#define DD 768
#define PP 20
#define BLKB 2688   // bytes per 32-d block (32*80 + 7*16 + pad, 16B aligned)
#define ROWS_PER_BLOCK 28
#define THREADS 224

typedef unsigned long long u64;

__device__ __forceinline__ int w2t_off(int d) {
    int b = d >> 5;
    int dl = d & 31;
    return b * BLKB + dl * 80 + ((dl >> 2) & 7) * 16;
}

__device__ __forceinline__ u64 pack2(float x) {
    u64 r;
    asm("mov.b64 %0, {%1, %1};" : "=l"(r) : "f"(x));
    return r;
}
__device__ __forceinline__ float2 unpack2(u64 v) {
    float2 f;
    asm("mov.b64 {%0, %1}, %2;" : "=f"(f.x), "=f"(f.y) : "l"(v));
    return f;
}
__device__ __forceinline__ void fma2(u64& d, u64 a, u64 b) {
    asm("fma.rn.f32x2 %0, %1, %2, %0;" : "+l"(d) : "l"(a), "l"(b));
}
__device__ __forceinline__ u64 mul2(u64 a, u64 b) {
    u64 r;
    asm("mul.rn.f32x2 %0, %1, %2;" : "=l"(r) : "l"(a), "l"(b));
    return r;
}

extern "C" __global__ void __launch_bounds__(THREADS, 2)
atte_matchlay_kernel(const float* __restrict__ repres,
                     const float* __restrict__ max_att,
                     const float* __restrict__ weight,
                     float* __restrict__ out, int nrows)
{
    extern __shared__ char w2t[];  // swizzled [DD][PP] fp32, 64512 B

    // Stage w^2 transposed+swizzled: w2t[off(d) + 4p] = weight[p][d]^2
    for (int idx = threadIdx.x; idx < PP * DD; idx += THREADS) {
        int p = idx / DD;
        int d = idx - p * DD;
        float w = weight[idx];
        *(float*)(w2t + w2t_off(d) + p * 4) = w * w;
    }
    __syncthreads();

    const int warp = threadIdx.x >> 5;
    const int lane = threadIdx.x & 31;
    const int rg   = lane >> 3;   // row within warp (0..3)
    const int dl   = lane & 7;    // d-lane (0..7)
    const int row  = (blockIdx.x * 7 + warp) * 4 + rg;
    if (row >= nrows) return;

    const float4* __restrict__ rptr = (const float4*)(repres + (size_t)row * DD);
    const float4* __restrict__ mptr = (const float4*)(max_att + (size_t)row * DD);

    u64 acc_dot[10], acc_n1[10], acc_n2[10];
#pragma unroll
    for (int k = 0; k < 10; k++) {
        acc_dot[k] = 0ull; acc_n1[k] = 0ull; acc_n2[k] = 0ull;
    }

    // Each vec-iter: this lane handles 4 consecutive d at d0 = i*32 + dl*4.
    // 24 iters cover D=768 (8 d-lanes x 4 floats x 24 = 768).
    float4 r4 = rptr[dl];
    float4 m4 = mptr[dl];

#pragma unroll 2
    for (int i = 0; i < 24; i++) {
        // prefetch next (clamped; re-reads last tile harmlessly)
        int nx = (i < 23) ? (i + 1) : 23;
        float4 rn = rptr[nx * 8 + dl];
        float4 mn = mptr[nx * 8 + dl];

        const int d0 = i * 32 + dl * 4;
        float rv[4] = {r4.x, r4.y, r4.z, r4.w};
        float mv[4] = {m4.x, m4.y, m4.z, m4.w};

#pragma unroll
        for (int j = 0; j < 4; j++) {
            const int d = d0 + j;
            const ulonglong2* wp = (const ulonglong2*)(w2t + w2t_off(d));
            ulonglong2 wA = wp[0];  // p0..3  (two f32x2 pairs)
            ulonglong2 wB = wp[1];  // p4..7
            ulonglong2 wC = wp[2];  // p8..11
            ulonglong2 wD = wp[3];  // p12..15
            ulonglong2 wE = wp[4];  // p16..19
            u64 wv[10] = {wA.x, wA.y, wB.x, wB.y, wC.x, wC.y,
                          wD.x, wD.y, wE.x, wE.y};

            u64 r2 = pack2(rv[j]);
            u64 m2 = pack2(mv[j]);
            u64 rm = mul2(r2, m2);
            u64 rr = mul2(r2, r2);
            u64 mm = mul2(m2, m2);

#pragma unroll
            for (int k = 0; k < 10; k++) {
                fma2(acc_dot[k], rm, wv[k]);
                fma2(acc_n1[k],  rr, wv[k]);
                fma2(acc_n2[k],  mm, wv[k]);
            }
        }
        r4 = rn; m4 = mn;
    }

    // Unpack to 60 floats
    float dot[PP], n1[PP], n2[PP];
#pragma unroll
    for (int k = 0; k < 10; k++) {
        float2 a = unpack2(acc_dot[k]); dot[2*k] = a.x; dot[2*k+1] = a.y;
        float2 b = unpack2(acc_n1[k]);  n1[2*k]  = b.x; n1[2*k+1]  = b.y;
        float2 c = unpack2(acc_n2[k]);  n2[2*k]  = c.x; n2[2*k+1]  = c.y;
    }

    // Reduce across the 8 d-lanes of this row (xor within low 3 bits of lane)
#pragma unroll
    for (int p = 0; p < PP; p++) {
#pragma unroll
        for (int o = 1; o < 8; o <<= 1) {
            dot[p] += __shfl_xor_sync(0xffffffffu, dot[p], o);
            n1[p]  += __shfl_xor_sync(0xffffffffu, n1[p],  o);
            n2[p]  += __shfl_xor_sync(0xffffffffu, n2[p],  o);
        }
    }

    // All 8 lanes of the group hold full sums; each writes ~3 outputs.
    const float EPS = 1e-8f;
#pragma unroll
    for (int p0 = 0; p0 < PP; p0 += 8) {
        int p = p0 + dl;
        if (p < PP) {
            float a = fmaxf(sqrtf(n1[p]), EPS);
            float b = fmaxf(sqrtf(n2[p]), EPS);
            out[(size_t)row * PP + p] = dot[p] / (a * b);
        }
    }
}

extern "C" void kernel_launch(void* const* d_in, const int* in_sizes, int n_in,
                              void* d_out, int out_size) {
    const float* repres  = (const float*)d_in[0];
    const float* max_att = (const float*)d_in[1];
    const float* weight  = (const float*)d_in[2];
    float* out = (float*)d_out;

    int nrows = in_sizes[0] / DD;                 // 8192
    int smem  = (DD / 32) * BLKB;                 // 24 * 2688 = 64512 B

    cudaFuncSetAttribute(atte_matchlay_kernel,
                         cudaFuncAttributeMaxDynamicSharedMemorySize, smem);

    int grid = (nrows + ROWS_PER_BLOCK - 1) / ROWS_PER_BLOCK;  // 293
    atte_matchlay_kernel<<<grid, THREADS, smem>>>(repres, max_att, weight, out, nrows);
}

// round 13
// speedup vs baseline: 1.2221x; 1.2221x over previous
#include <cuda_runtime.h>

// AtteMatchLay: multi-perspective cosine similarity.
// out[n][p] = dot / (max(sqrt(n1),eps) * max(sqrt(n2),eps))
//   dot = sum_d r*m*w2, n1 = sum_d r^2*w2, n2 = sum_d m^2*w2, w2 = weight^2
// N = 8192, D = 768, P = 20. fp32.
//
// R12: occupancy push. R8 showed superlinear slowdown when warps/SM fell
// (latency-bound cliff), so split P across warp-groups to shrink the
// accumulator footprint and fit 3 CTAs/SM (24 warps/SM, was 16):
//   warps 0-3: p0..11  (6 f32x2 pairs, 3x LDS.128 of w2 per d)
//   warps 4-7: p12..19 (4 pairs, 2x LDS.128 per d), SAME 16 rows per block.
// Duplicate r/m reads of the second group hit L1/L2 (co-resident) -> DRAM
// traffic unchanged. w2t layout = proven R7 block-local swizzle (injective,
// conflict-free; sub-offsets +48/+64 stay 16B-aligned and conflict-free).

#define DD 768
#define PP 20
#define BLKB 2688   // bytes per 32-d swizzle block
#define THREADS 256

typedef unsigned long long u64;

__device__ __forceinline__ int w2t_off(int d) {
    int b = d >> 5;
    int dl = d & 31;
    return b * BLKB + dl * 80 + ((dl >> 2) & 7) * 16;
}

__device__ __forceinline__ u64 pack2(float x) {
    u64 r;
    asm("mov.b64 %0, {%1, %1};" : "=l"(r) : "f"(x));
    return r;
}
__device__ __forceinline__ float2 unpack2(u64 v) {
    float2 f;
    asm("mov.b64 {%0, %1}, %2;" : "=f"(f.x), "=f"(f.y) : "l"(v));
    return f;
}
__device__ __forceinline__ void fma2(u64& d, u64 a, u64 b) {
    asm("fma.rn.f32x2 %0, %1, %2, %0;" : "+l"(d) : "l"(a), "l"(b));
}

// One warp: 4 rows x 8 d-lanes, full D sweep, NP f32x2 p-pairs starting at
// byte offset POFF within each w2t d-row. NP*16B loads are 16B-aligned.
template<int NP, int POFF>
__device__ __forceinline__ void compute_rows(
    const char* __restrict__ w2t,
    const float* __restrict__ repres,
    const float* __restrict__ max_att,
    float* __restrict__ out,
    int row, int dl)
{
    const float4* __restrict__ rptr = (const float4*)(repres + (size_t)row * DD);
    const float4* __restrict__ mptr = (const float4*)(max_att + (size_t)row * DD);

    u64 acc_dot[NP], acc_n1[NP], acc_n2[NP];
#pragma unroll
    for (int k = 0; k < NP; k++) {
        acc_dot[k] = 0ull; acc_n1[k] = 0ull; acc_n2[k] = 0ull;
    }

    // 24 i-iters x (8 lanes x 4 floats) = 768 d
#pragma unroll 4
    for (int i = 0; i < 24; i++) {
        float4 r4 = rptr[i * 8 + dl];
        float4 m4 = mptr[i * 8 + dl];
        const int d0 = i * 32 + dl * 4;
        float rv[4] = {r4.x, r4.y, r4.z, r4.w};
        float mv[4] = {m4.x, m4.y, m4.z, m4.w};

#pragma unroll
        for (int j = 0; j < 4; j++) {
            const char* base = w2t + w2t_off(d0 + j) + POFF;
            u64 wv[NP];
#pragma unroll
            for (int q = 0; q < NP / 2; q++) {
                ulonglong2 w = *(const ulonglong2*)(base + q * 16);
                wv[2 * q]     = w.x;
                wv[2 * q + 1] = w.y;
            }

            float r = rv[j], m = mv[j];
            u64 rm = pack2(r * m);
            u64 rr = pack2(r * r);
            u64 mm = pack2(m * m);

#pragma unroll
            for (int k = 0; k < NP; k++) {
                fma2(acc_dot[k], rm, wv[k]);
                fma2(acc_n1[k],  rr, wv[k]);
                fma2(acc_n2[k],  mm, wv[k]);
            }
        }
    }

    // Unpack and reduce across the 8 d-lanes of this row
    const int NPF = 2 * NP;
    float dot[NPF], n1[NPF], n2[NPF];
#pragma unroll
    for (int k = 0; k < NP; k++) {
        float2 a = unpack2(acc_dot[k]); dot[2*k] = a.x; dot[2*k+1] = a.y;
        float2 b = unpack2(acc_n1[k]);  n1[2*k]  = b.x; n1[2*k+1]  = b.y;
        float2 c = unpack2(acc_n2[k]);  n2[2*k]  = c.x; n2[2*k+1]  = c.y;
    }
#pragma unroll
    for (int p = 0; p < NPF; p++) {
#pragma unroll
        for (int o = 1; o < 8; o <<= 1) {
            dot[p] += __shfl_xor_sync(0xffffffffu, dot[p], o);
            n1[p]  += __shfl_xor_sync(0xffffffffu, n1[p],  o);
            n2[p]  += __shfl_xor_sync(0xffffffffu, n2[p],  o);
        }
    }

    const float EPS = 1e-8f;
    const int PBASE = POFF / 4;  // first p of this group
#pragma unroll
    for (int p0 = 0; p0 < NPF; p0 += 8) {
        int p = p0 + dl;
        if (p < NPF) {
            float a = fmaxf(sqrtf(n1[p]), EPS);
            float b = fmaxf(sqrtf(n2[p]), EPS);
            out[(size_t)row * PP + PBASE + p] = dot[p] / (a * b);
        }
    }
}

extern "C" __global__ void __launch_bounds__(THREADS, 3)
atte_matchlay_kernel(const float* __restrict__ repres,
                     const float* __restrict__ max_att,
                     const float* __restrict__ weight,
                     float* __restrict__ out, int nrows)
{
    extern __shared__ char w2t[];  // swizzled [DD][20] fp32, 64512 B

    for (int idx = threadIdx.x; idx < PP * DD; idx += THREADS) {
        int p = idx / DD;
        int d = idx - p * DD;
        float w = weight[idx];
        *(float*)(w2t + w2t_off(d) + p * 4) = w * w;
    }
    __syncthreads();

    const int warp = threadIdx.x >> 5;
    const int lane = threadIdx.x & 31;
    const int pg   = warp >> 2;   // 0: p0..11, 1: p12..19
    const int rw   = warp & 3;    // row-warp within group
    const int rg   = lane >> 3;   // row within warp (0..3)
    const int dl   = lane & 7;    // d-lane (0..7)
    const int row  = (blockIdx.x * 4 + rw) * 4 + rg;  // 16 rows per block
    if (row >= nrows) return;

    if (pg == 0)
        compute_rows<6, 0>(w2t, repres, max_att, out, row, dl);
    else
        compute_rows<4, 48>(w2t, repres, max_att, out, row, dl);
}

extern "C" void kernel_launch(void* const* d_in, const int* in_sizes, int n_in,
                              void* d_out, int out_size) {
    const float* repres  = (const float*)d_in[0];
    const float* max_att = (const float*)d_in[1];
    const float* weight  = (const float*)d_in[2];
    float* out = (float*)d_out;

    int nrows = in_sizes[0] / DD;          // 8192
    int smem  = (DD / 32) * BLKB;          // 64512 B

    cudaFuncSetAttribute(atte_matchlay_kernel,
                         cudaFuncAttributeMaxDynamicSharedMemorySize, smem);

    int grid = (nrows + 15) / 16;          // 512
    atte_matchlay_kernel<<<grid, THREADS, smem>>>(repres, max_att, weight, out, nrows);
}

// round 14
// speedup vs baseline: 1.3924x; 1.1393x over previous
#include <cuda_runtime.h>

// AtteMatchLay: multi-perspective cosine similarity.
// out[n][p] = dot / (max(sqrt(n1),eps) * max(sqrt(n2),eps))
//   dot = sum_d r*m*w2, n1 = sum_d r^2*w2, n2 = sum_d m^2*w2, w2 = weight^2
// N = 8192, D = 768, P = 20. fp32.
//
// R14: L1tex-byte reduction. Evidence R7/R8/R12: time tracks L1% (always top
// pipe), not occupancy or fma%. An LDS.128 with 32 lanes requesting 16B costs
// ~4 crossbar wavefronts (512B lane-requests / 128B per cyc) -- broadcast
// kills conflicts, not bytes. Fix: each thread accumulates TWO rows per wv
// load -> LDS bytes and instructions per (row,d) halved (80B/5-loads ->
// 40B/2.5-loads), FFMA2 total unchanged.
//   warps 0-3: p0..11 (6 pairs), warps 4-7: p12..19 (4 pairs)
//   warp = 4 row-slots x 8 d-lanes, each slot = 2 rows -> 8 rows/warp,
//   block = 32 rows, grid = 256 (one wave at 2 CTAs/SM).
// w2t layout: proven R7 block-local swizzle (injective, conflict-free).

#define DD 768
#define PP 20
#define BLKB 2688   // bytes per 32-d swizzle block
#define THREADS 256

typedef unsigned long long u64;

__device__ __forceinline__ int w2t_off(int d) {
    int b = d >> 5;
    int dl = d & 31;
    return b * BLKB + dl * 80 + ((dl >> 2) & 7) * 16;
}

__device__ __forceinline__ u64 pack2(float x) {
    u64 r;
    asm("mov.b64 %0, {%1, %1};" : "=l"(r) : "f"(x));
    return r;
}
__device__ __forceinline__ float2 unpack2(u64 v) {
    float2 f;
    asm("mov.b64 {%0, %1}, %2;" : "=f"(f.x), "=f"(f.y) : "l"(v));
    return f;
}
__device__ __forceinline__ void fma2(u64& d, u64 a, u64 b) {
    asm("fma.rn.f32x2 %0, %1, %2, %0;" : "+l"(d) : "l"(a), "l"(b));
}
__device__ __forceinline__ u64 mul2(u64 a, u64 b) {
    u64 r;
    asm("mul.rn.f32x2 %0, %1, %2;" : "=l"(r) : "l"(a), "l"(b));
    return r;
}

// One warp-thread: TWO rows (row, row+1) x NP f32x2 p-pairs at byte offset
// POFF in each w2t d-row. 8 d-lanes sweep D; reduce; write both rows.
template<int NP, int POFF>
__device__ __forceinline__ void compute_rows2(
    const char* __restrict__ w2t,
    const float* __restrict__ repres,
    const float* __restrict__ max_att,
    float* __restrict__ out,
    int row, int dl)
{
    const float4* __restrict__ rptr0 = (const float4*)(repres + (size_t)row * DD);
    const float4* __restrict__ mptr0 = (const float4*)(max_att + (size_t)row * DD);
    const float4* __restrict__ rptr1 = (const float4*)(repres + (size_t)(row + 1) * DD);
    const float4* __restrict__ mptr1 = (const float4*)(max_att + (size_t)(row + 1) * DD);

    u64 aD[2][NP], aN1[2][NP], aN2[2][NP];
#pragma unroll
    for (int t = 0; t < 2; t++)
#pragma unroll
        for (int k = 0; k < NP; k++) {
            aD[t][k] = 0ull; aN1[t][k] = 0ull; aN2[t][k] = 0ull;
        }

    // 24 i-iters x (8 lanes x 4 floats) = 768 d
#pragma unroll 2
    for (int i = 0; i < 24; i++) {
        float4 rA = rptr0[i * 8 + dl];
        float4 mA = mptr0[i * 8 + dl];
        float4 rB = rptr1[i * 8 + dl];
        float4 mB = mptr1[i * 8 + dl];
        const int d0 = i * 32 + dl * 4;
        float rvA[4] = {rA.x, rA.y, rA.z, rA.w};
        float mvA[4] = {mA.x, mA.y, mA.z, mA.w};
        float rvB[4] = {rB.x, rB.y, rB.z, rB.w};
        float mvB[4] = {mB.x, mB.y, mB.z, mB.w};

#pragma unroll
        for (int j = 0; j < 4; j++) {
            const char* base = w2t + w2t_off(d0 + j) + POFF;
            u64 wv[NP];
#pragma unroll
            for (int q = 0; q < NP / 2; q++) {
                ulonglong2 w = *(const ulonglong2*)(base + q * 16);
                wv[2 * q]     = w.x;
                wv[2 * q + 1] = w.y;
            }

            u64 r2A = pack2(rvA[j]), m2A = pack2(mvA[j]);
            u64 rmA = mul2(r2A, m2A), rrA = mul2(r2A, r2A), mmA = mul2(m2A, m2A);
            u64 r2B = pack2(rvB[j]), m2B = pack2(mvB[j]);
            u64 rmB = mul2(r2B, m2B), rrB = mul2(r2B, r2B), mmB = mul2(m2B, m2B);

#pragma unroll
            for (int k = 0; k < NP; k++) {
                fma2(aD[0][k],  rmA, wv[k]);
                fma2(aN1[0][k], rrA, wv[k]);
                fma2(aN2[0][k], mmA, wv[k]);
                fma2(aD[1][k],  rmB, wv[k]);
                fma2(aN1[1][k], rrB, wv[k]);
                fma2(aN2[1][k], mmB, wv[k]);
            }
        }
    }

    const int NPF = 2 * NP;
    const float EPS = 1e-8f;
    const int PBASE = POFF / 4;

#pragma unroll
    for (int t = 0; t < 2; t++) {
        float dot[NPF], n1[NPF], n2[NPF];
#pragma unroll
        for (int k = 0; k < NP; k++) {
            float2 a = unpack2(aD[t][k]);  dot[2*k] = a.x; dot[2*k+1] = a.y;
            float2 b = unpack2(aN1[t][k]); n1[2*k]  = b.x; n1[2*k+1]  = b.y;
            float2 c = unpack2(aN2[t][k]); n2[2*k]  = c.x; n2[2*k+1]  = c.y;
        }
#pragma unroll
        for (int p = 0; p < NPF; p++) {
#pragma unroll
            for (int o = 1; o < 8; o <<= 1) {
                dot[p] += __shfl_xor_sync(0xffffffffu, dot[p], o);
                n1[p]  += __shfl_xor_sync(0xffffffffu, n1[p],  o);
                n2[p]  += __shfl_xor_sync(0xffffffffu, n2[p],  o);
            }
        }
#pragma unroll
        for (int p0 = 0; p0 < NPF; p0 += 8) {
            int p = p0 + dl;
            if (p < NPF) {
                float a = fmaxf(sqrtf(n1[p]), EPS);
                float b = fmaxf(sqrtf(n2[p]), EPS);
                out[(size_t)(row + t) * PP + PBASE + p] = dot[p] / (a * b);
            }
        }
    }
}

extern "C" __global__ void __launch_bounds__(THREADS, 2)
atte_matchlay_kernel(const float* __restrict__ repres,
                     const float* __restrict__ max_att,
                     const float* __restrict__ weight,
                     float* __restrict__ out, int nrows)
{
    extern __shared__ char w2t[];  // swizzled [DD][20] fp32, 64512 B

    for (int idx = threadIdx.x; idx < PP * DD; idx += THREADS) {
        int p = idx / DD;
        int d = idx - p * DD;
        float w = weight[idx];
        *(float*)(w2t + w2t_off(d) + p * 4) = w * w;
    }
    __syncthreads();

    const int warp = threadIdx.x >> 5;
    const int lane = threadIdx.x & 31;
    const int pg   = warp >> 2;   // 0: p0..11, 1: p12..19
    const int rw   = warp & 3;    // row-warp within group
    const int rg   = lane >> 3;   // row-slot within warp (0..3)
    const int dl   = lane & 7;    // d-lane (0..7)
    // block covers 32 rows; warp covers 8 (4 slots x 2 rows)
    const int row  = blockIdx.x * 32 + rw * 8 + rg * 2;
    if (row >= nrows) return;

    if (pg == 0)
        compute_rows2<6, 0>(w2t, repres, max_att, out, row, dl);
    else
        compute_rows2<4, 48>(w2t, repres, max_att, out, row, dl);
}

extern "C" void kernel_launch(void* const* d_in, const int* in_sizes, int n_in,
                              void* d_out, int out_size) {
    const float* repres  = (const float*)d_in[0];
    const float* max_att = (const float*)d_in[1];
    const float* weight  = (const float*)d_in[2];
    float* out = (float*)d_out;

    int nrows = in_sizes[0] / DD;          // 8192
    int smem  = (DD / 32) * BLKB;          // 64512 B

    cudaFuncSetAttribute(atte_matchlay_kernel,
                         cudaFuncAttributeMaxDynamicSharedMemorySize, smem);

    int grid = (nrows + 31) / 32;          // 256
    atte_matchlay_kernel<<<grid, THREADS, smem>>>(repres, max_att, weight, out, nrows);
}